// round 5
// baseline (speedup 1.0000x reference)
#include <cuda_runtime.h>
#include <cstdint>

// SoftCountPixels: Y[b,p] = (1/(H*W)) * sum_{h,w} exp(-||x[b,:,h,w] - P[p,:]||_2 / 0.6)
// x: (16, 3, 256, 256) f32 planar; P: (32, 3) f32; out: (16, 32) f32
//
// exp(-d/0.6) = ex2(-sqrt(K2*d^2)), K2 = (log2e/0.6)^2: pre-scaled quadratic
// form kills the FMUL before EX2; |.| and neg fold into MUFU source modifiers.
// Pair-side FMA work is packed f32x2 (2 pixels / instruction). Channel data is
// loaded as ulonglong2 so the two-pixel packs come straight out of LDG.128 —
// zero pack instructions; the unpack before MUFU is register renaming.
// Binding resource: MUFU pipe (SQRT+EX2, 2 per pair, rt_SMSP=8).

#define B 16
#define HW (256 * 256)
#define HW4 (HW / 4)             // in ulonglong2 (4-pixel) units
#define NPRO 32
#define PPT 4                    // protos per thread
#define PGROUPS (NPRO / PPT)     // 8
#define THREADS 256
#define CHUNKS 3                 // 3*16*8 = 384 blocks <= 444 slots @ 3 CTA/SM -> 1 wave

#define K2 5.781580510735007f    // (log2(e)/0.6)^2

__device__ __forceinline__ float fast_sqrt(float v) {
    float r;
    asm("sqrt.approx.f32 %0, %1;" : "=f"(r) : "f"(v));
    return r;
}
__device__ __forceinline__ float fast_ex2(float v) {
    float r;
    asm("ex2.approx.f32 %0, %1;" : "=f"(r) : "f"(v));
    return r;
}

// ---- packed f32x2 helpers ----
__device__ __forceinline__ uint64_t pack2(float lo, float hi) {
    uint64_t r;
    asm("mov.b64 %0, {%1, %2};" : "=l"(r) : "f"(lo), "f"(hi));
    return r;
}
__device__ __forceinline__ void unpack2(uint64_t v, float& lo, float& hi) {
    asm("mov.b64 {%0, %1}, %2;" : "=f"(lo), "=f"(hi) : "l"(v));
}
__device__ __forceinline__ uint64_t fma2(uint64_t a, uint64_t b, uint64_t c) {
    uint64_t r;
    asm("fma.rn.f32x2 %0, %1, %2, %3;" : "=l"(r) : "l"(a), "l"(b), "l"(c));
    return r;
}
__device__ __forceinline__ uint64_t add2(uint64_t a, uint64_t b) {
    uint64_t r;
    asm("add.rn.f32x2 %0, %1, %2;" : "=l"(r) : "l"(a), "l"(b));
    return r;
}
__device__ __forceinline__ uint64_t mul2(uint64_t a, uint64_t b) {
    uint64_t r;
    asm("mul.rn.f32x2 %0, %1, %2;" : "=l"(r) : "l"(a), "l"(b));
    return r;
}

__global__ void zero_out_kernel(float* out, int n) {
    int i = blockIdx.x * blockDim.x + threadIdx.x;
    if (i < n) out[i] = 0.0f;
}

__global__ __launch_bounds__(THREADS, 3)
void softcount_kernel(const float* __restrict__ x,
                      const float* __restrict__ P,
                      float* __restrict__ out) {
    __shared__ float sacc[PPT];

    const int tid = threadIdx.x;
    const int b   = blockIdx.y;
    const int pg  = blockIdx.z;

    // Packed (broadcast) per-proto constants, pre-scaled by K2.
    uint64_t qk0[PPT], qk1[PPT], qk2[PPT], cck[PPT];
    float accA[PPT], accB[PPT];
#pragma unroll
    for (int i = 0; i < PPT; i++) {
        const int p = pg * PPT + i;
        const float p0 = P[p * 3 + 0];
        const float p1 = P[p * 3 + 1];
        const float p2 = P[p * 3 + 2];
        const float q0 = -2.0f * K2 * p0;
        const float q1 = -2.0f * K2 * p1;
        const float q2 = -2.0f * K2 * p2;
        const float cc = K2 * (p0 * p0 + p1 * p1 + p2 * p2);
        qk0[i] = pack2(q0, q0);
        qk1[i] = pack2(q1, q1);
        qk2[i] = pack2(q2, q2);
        cck[i] = pack2(cc, cc);
        accA[i] = 0.0f;
        accB[i] = 0.0f;
    }
    const uint64_t K2_2 = pack2(K2, K2);
    if (tid < PPT) sacc[tid] = 0.0f;
    __syncthreads();

    // Channel planes viewed as 4-pixel (16B) vectors: .x = pixels(0,1) packed
    // f32x2, .y = pixels(2,3) — packs come straight out of LDG.128.
    const ulonglong2* xc0 = (const ulonglong2*)(x + (size_t)b * 3 * HW)
                            + (size_t)blockIdx.x * THREADS + tid;
    const ulonglong2* xc1 = xc0 + HW4;
    const ulonglong2* xc2 = xc1 + HW4;
    const int iters = HW4 / (CHUNKS * THREADS);      // 16384 / 768 -> not exact!
    // HW4 = 16384; CHUNKS*THREADS = 768 -> 16384 = 21*768 + 256. Use guarded loop.
    int idx = blockIdx.x * THREADS + tid;

    for (; idx < HW4; idx += CHUNKS * THREADS,
                      xc0 += CHUNKS * THREADS, xc1 += CHUNKS * THREADS, xc2 += CHUNKS * THREADS) {
        const ulonglong2 c0 = *xc0;
        const ulonglong2 c1 = *xc1;
        const ulonglong2 c2 = *xc2;

        // ---- pixel pair (0,1) ----
        {
            const uint64_t X0 = c0.x, X1 = c1.x, X2 = c2.x;
            uint64_t xx = mul2(X0, X0);
            xx = fma2(X1, X1, xx);
            xx = fma2(X2, X2, xx);
            const uint64_t xxk = mul2(K2_2, xx);
#pragma unroll
            for (int i = 0; i < PPT; i++) {
                uint64_t t = add2(cck[i], xxk);
                t = fma2(qk0[i], X0, t);
                t = fma2(qk1[i], X1, t);
                t = fma2(qk2[i], X2, t);
                float ta, tb;
                unpack2(t, ta, tb);
                accA[i] += fast_ex2(-fast_sqrt(fabsf(ta)));
                accB[i] += fast_ex2(-fast_sqrt(fabsf(tb)));
            }
        }
        // ---- pixel pair (2,3) ----
        {
            const uint64_t X0 = c0.y, X1 = c1.y, X2 = c2.y;
            uint64_t xx = mul2(X0, X0);
            xx = fma2(X1, X1, xx);
            xx = fma2(X2, X2, xx);
            const uint64_t xxk = mul2(K2_2, xx);
#pragma unroll
            for (int i = 0; i < PPT; i++) {
                uint64_t t = add2(cck[i], xxk);
                t = fma2(qk0[i], X0, t);
                t = fma2(qk1[i], X1, t);
                t = fma2(qk2[i], X2, t);
                float ta, tb;
                unpack2(t, ta, tb);
                accA[i] += fast_ex2(-fast_sqrt(fabsf(ta)));
                accB[i] += fast_ex2(-fast_sqrt(fabsf(tb)));
            }
        }
    }
    (void)iters;

    // Reduce: warp shuffle, shared atomics, one global atomic per (b,p) per block.
    const int lane = tid & 31;
#pragma unroll
    for (int i = 0; i < PPT; i++) {
        float v = accA[i] + accB[i];
#pragma unroll
        for (int off = 16; off > 0; off >>= 1)
            v += __shfl_xor_sync(0xFFFFFFFFu, v, off);
        if (lane == 0) atomicAdd(&sacc[i], v);
    }
    __syncthreads();

    if (tid < PPT) {
        atomicAdd(&out[b * NPRO + pg * PPT + tid], sacc[tid] * (1.0f / (float)HW));
    }
}

extern "C" void kernel_launch(void* const* d_in, const int* in_sizes, int n_in,
                              void* d_out, int out_size) {
    const float* x = (const float*)d_in[0];
    const float* P = (const float*)d_in[1];
    float* out = (float*)d_out;

    zero_out_kernel<<<(out_size + 255) / 256, 256>>>(out, out_size);

    dim3 grid(CHUNKS, B, PGROUPS);
    softcount_kernel<<<grid, THREADS>>>(x, P, out);
}

// round 6
// speedup vs baseline: 1.0569x; 1.0569x over previous
#include <cuda_runtime.h>
#include <cstdint>

// SoftCountPixels: Y[b,p] = (1/(H*W)) * sum_{h,w} exp(-||x[b,:,h,w] - P[p,:]||_2 / 0.6)
// x: (16, 3, 256, 256) f32 planar; P: (32, 3) f32; out: (16, 32) f32
//
// exp(-d/0.6) = ex2(-sqrt(K2*d^2)), K2=(log2e/0.6)^2: pre-scaled quadratic form,
// |.| and neg fold into MUFU source modifiers. Packed f32x2 pair math (2 pixels
// per instruction). KEY CHANGE vs R5: software-pipelined register prefetch —
// next iteration's 3 channel loads are issued BEFORE processing the current
// data, hiding L2/DRAM latency that was previously exposed at the loop top.

#define B 16
#define HW (256 * 256)
#define HW4 (HW / 4)             // 16384 four-pixel vectors per channel
#define NPRO 32
#define PPT 4                    // protos per thread
#define PGROUPS (NPRO / PPT)     // 8
#define THREADS 256
#define CHUNKS 3                 // 3*16*8 = 384 blocks <= 444 slots @ 3 CTA/SM -> 1 wave
#define STRIDE (CHUNKS * THREADS)

#define K2 5.781580510735007f    // (log2(e)/0.6)^2

__device__ __forceinline__ float fast_sqrt(float v) {
    float r;
    asm("sqrt.approx.f32 %0, %1;" : "=f"(r) : "f"(v));
    return r;
}
__device__ __forceinline__ float fast_ex2(float v) {
    float r;
    asm("ex2.approx.f32 %0, %1;" : "=f"(r) : "f"(v));
    return r;
}

// ---- packed f32x2 helpers ----
__device__ __forceinline__ uint64_t pack2(float lo, float hi) {
    uint64_t r;
    asm("mov.b64 %0, {%1, %2};" : "=l"(r) : "f"(lo), "f"(hi));
    return r;
}
__device__ __forceinline__ void unpack2(uint64_t v, float& lo, float& hi) {
    asm("mov.b64 {%0, %1}, %2;" : "=f"(lo), "=f"(hi) : "l"(v));
}
__device__ __forceinline__ uint64_t fma2(uint64_t a, uint64_t b, uint64_t c) {
    uint64_t r;
    asm("fma.rn.f32x2 %0, %1, %2, %3;" : "=l"(r) : "l"(a), "l"(b), "l"(c));
    return r;
}
__device__ __forceinline__ uint64_t add2(uint64_t a, uint64_t b) {
    uint64_t r;
    asm("add.rn.f32x2 %0, %1, %2;" : "=l"(r) : "l"(a), "l"(b));
    return r;
}
__device__ __forceinline__ uint64_t mul2(uint64_t a, uint64_t b) {
    uint64_t r;
    asm("mul.rn.f32x2 %0, %1, %2;" : "=l"(r) : "l"(a), "l"(b));
    return r;
}

__global__ void zero_out_kernel(float* out, int n) {
    int i = blockIdx.x * blockDim.x + threadIdx.x;
    if (i < n) out[i] = 0.0f;
}

__global__ __launch_bounds__(THREADS, 3)
void softcount_kernel(const float* __restrict__ x,
                      const float* __restrict__ P,
                      float* __restrict__ out) {
    __shared__ float sacc[PPT];

    const int tid = threadIdx.x;
    const int b   = blockIdx.y;
    const int pg  = blockIdx.z;

    // Packed (broadcast) per-proto constants, pre-scaled by K2.
    uint64_t qk0[PPT], qk1[PPT], qk2[PPT], cck[PPT];
    float acc[PPT];
#pragma unroll
    for (int i = 0; i < PPT; i++) {
        const int p = pg * PPT + i;
        const float p0 = P[p * 3 + 0];
        const float p1 = P[p * 3 + 1];
        const float p2 = P[p * 3 + 2];
        const float q0 = -2.0f * K2 * p0;
        const float q1 = -2.0f * K2 * p1;
        const float q2 = -2.0f * K2 * p2;
        const float cc = K2 * (p0 * p0 + p1 * p1 + p2 * p2);
        qk0[i] = pack2(q0, q0);
        qk1[i] = pack2(q1, q1);
        qk2[i] = pack2(q2, q2);
        cck[i] = pack2(cc, cc);
        acc[i] = 0.0f;
    }
    const uint64_t K2_2 = pack2(K2, K2);
    if (tid < PPT) sacc[tid] = 0.0f;
    __syncthreads();

    // Single base pointer; channel planes at immediate offsets (HW4, 2*HW4).
    const ulonglong2* xb = (const ulonglong2*)(x + (size_t)b * 3 * HW);

    int idx = blockIdx.x * THREADS + tid;   // every thread has >= 1 element

    // Pipeline prologue: load iteration 0.
    ulonglong2 c0 = xb[idx];
    ulonglong2 c1 = xb[idx + HW4];
    ulonglong2 c2 = xb[idx + 2 * HW4];

    while (true) {
        // ---- prefetch next iteration (clamped: result unused on last iter) ----
        const int nidx = idx + STRIDE;
        const bool more = (nidx < HW4);
        const int safe = more ? nidx : idx;
        const ulonglong2 n0 = xb[safe];
        const ulonglong2 n1 = xb[safe + HW4];
        const ulonglong2 n2 = xb[safe + 2 * HW4];

        // ---- process current: pixel pair (0,1) ----
        {
            const uint64_t X0 = c0.x, X1 = c1.x, X2 = c2.x;
            uint64_t xx = mul2(X0, X0);
            xx = fma2(X1, X1, xx);
            xx = fma2(X2, X2, xx);
            const uint64_t xxk = mul2(K2_2, xx);
#pragma unroll
            for (int i = 0; i < PPT; i++) {
                uint64_t t = add2(cck[i], xxk);
                t = fma2(qk0[i], X0, t);
                t = fma2(qk1[i], X1, t);
                t = fma2(qk2[i], X2, t);
                float ta, tb;
                unpack2(t, ta, tb);
                acc[i] += fast_ex2(-fast_sqrt(fabsf(ta)));
                acc[i] += fast_ex2(-fast_sqrt(fabsf(tb)));
            }
        }
        // ---- process current: pixel pair (2,3) ----
        {
            const uint64_t X0 = c0.y, X1 = c1.y, X2 = c2.y;
            uint64_t xx = mul2(X0, X0);
            xx = fma2(X1, X1, xx);
            xx = fma2(X2, X2, xx);
            const uint64_t xxk = mul2(K2_2, xx);
#pragma unroll
            for (int i = 0; i < PPT; i++) {
                uint64_t t = add2(cck[i], xxk);
                t = fma2(qk0[i], X0, t);
                t = fma2(qk1[i], X1, t);
                t = fma2(qk2[i], X2, t);
                float ta, tb;
                unpack2(t, ta, tb);
                acc[i] += fast_ex2(-fast_sqrt(fabsf(ta)));
                acc[i] += fast_ex2(-fast_sqrt(fabsf(tb)));
            }
        }

        if (!more) break;
        idx = nidx;
        c0 = n0; c1 = n1; c2 = n2;
    }

    // Reduce: warp shuffle, shared atomics, one global atomic per (b,p) per block.
    const int lane = tid & 31;
#pragma unroll
    for (int i = 0; i < PPT; i++) {
        float v = acc[i];
#pragma unroll
        for (int off = 16; off > 0; off >>= 1)
            v += __shfl_xor_sync(0xFFFFFFFFu, v, off);
        if (lane == 0) atomicAdd(&sacc[i], v);
    }
    __syncthreads();

    if (tid < PPT) {
        atomicAdd(&out[b * NPRO + pg * PPT + tid], sacc[tid] * (1.0f / (float)HW));
    }
}

extern "C" void kernel_launch(void* const* d_in, const int* in_sizes, int n_in,
                              void* d_out, int out_size) {
    const float* x = (const float*)d_in[0];
    const float* P = (const float*)d_in[1];
    float* out = (float*)d_out;

    zero_out_kernel<<<(out_size + 255) / 256, 256>>>(out, out_size);

    dim3 grid(CHUNKS, B, PGROUPS);
    softcount_kernel<<<grid, THREADS>>>(x, P, out);
}